// round 13
// baseline (speedup 1.0000x reference)
#include <cuda_runtime.h>
#include <math.h>

#define NTOT 4992
#define BB 128
#define HN 39
#define WN 39
#define POS 1521      // 39*39
#define E0 200064     // B*E_PER
#define ET 205056     // E0 + NTOT self loops
#define HEADS 8
#define HID 64
#define OUTC 64
#define F1 78
#define D1 512
#define CAP 128       // per-dst CSR bucket capacity

// ---------------- scratch (static device memory; no allocation) ----------------
__device__ float d_x1[BB*8*POS];
__device__ float d_gi[3*HN*NTOT];
__device__ float d_xnT[F1*NTOT];
__device__ __align__(2048) float d_xl1[NTOT*D1];
__device__ float d_xr1[NTOT*D1];
__device__ float d_h1[NTOT*D1];
__device__ float d_xl2[NTOT*OUTC];
__device__ float d_xr2[NTOT*OUTC];
__device__ int   d_cur[NTOT];
__device__ int   d_csr[NTOT*CAP];

__device__ __forceinline__ float nz(float v){ return isnan(v) ? 0.0f : v; }
__device__ __forceinline__ float fast_tanh(float x){
    float r; asm("tanh.approx.f32 %0, %1;" : "=f"(r) : "f"(x)); return r;
}

// ------ f32x2 packed math helpers ------
__device__ __forceinline__ unsigned long long pack2(float lo, float hi){
    unsigned long long r;
    asm("mov.b64 %0, {%1,%2};" : "=l"(r) : "f"(lo), "f"(hi));
    return r;
}
__device__ __forceinline__ unsigned long long fma2(unsigned long long a,
                                                   unsigned long long b,
                                                   unsigned long long c){
    unsigned long long d;
    asm("fma.rn.f32x2 %0, %1, %2, %3;" : "=l"(d) : "l"(a), "l"(b), "l"(c));
    return d;
}
__device__ __forceinline__ void unpack2(unsigned long long v, float& lo, float& hi){
    asm("mov.b64 {%0,%1}, %2;" : "=f"(lo), "=f"(hi) : "l"(v));
}

// ---------------- init: zero bucket counters ----------------
__global__ void k_init(){
    int i = blockIdx.x*blockDim.x + threadIdx.x;
    if (i < NTOT) d_cur[i] = 0;
}

// ---------------- conv1 (1x1, 3->8) + BN + ReLU, fused man-feature copy ----------------
__global__ void k_conv1(const float* __restrict__ man, const float* __restrict__ ac,
                        const float* __restrict__ ve, const float* __restrict__ maskv,
                        const float* __restrict__ w1, const float* __restrict__ b1,
                        const float* __restrict__ g1, const float* __restrict__ bb1){
    int idx = blockIdx.x*blockDim.x + threadIdx.x;
    if (idx >= BB*POS) return;
    int b = idx / POS, p = idx % POS;
    float c0 = nz(man[idx]), c1 = nz(ac[idx]), c2 = nz(ve[idx]);
    int f = p / WN, j = p % WN;
    int node = b*WN + j;
    d_xnT[f*NTOT + node] = c0 * maskv[node];
    const float inv = rsqrtf(1.0f + 1e-5f);
    #pragma unroll
    for (int o=0;o<8;o++){
        float v = w1[o*3+0]*c0 + w1[o*3+1]*c1 + w1[o*3+2]*c2 + b1[o];
        v = v * (g1[o]*inv) + bb1[o];
        d_x1[(b*8+o)*POS + p] = fmaxf(v, 0.0f);
    }
}

// ---------------- conv2 (3x3 pad1, 8->16) + BN + GRU input projection (16->3) ----------------
__global__ void k_conv2(const float* __restrict__ w2, const float* __restrict__ b2,
                        const float* __restrict__ g2, const float* __restrict__ bb2,
                        const float* __restrict__ wih, const float* __restrict__ bih){
    __shared__ unsigned long long sw2p[72][8];
    __shared__ float ssc[16], sof[16];
    __shared__ float swih[48];
    int tid = threadIdx.x;
    for (int i=tid;i<576;i+=blockDim.x){
        int tap = i>>3, op = i&7;
        sw2p[tap][op] = pack2(w2[(2*op)*72+tap], w2[(2*op+1)*72+tap]);
    }
    if (tid<16){ float s = g2[tid]*rsqrtf(1.0f+1e-5f); ssc[tid]=s; sof[tid]=b2[tid]*s + bb2[tid]; }
    if (tid<48) swih[tid]=wih[tid];
    __syncthreads();
    int b = blockIdx.x;
    int p = blockIdx.y*blockDim.x + tid;
    if (p >= POS) return;
    int i = p / WN, j = p % WN;
    unsigned long long acc2[8] = {0ull,0ull,0ull,0ull,0ull,0ull,0ull,0ull};
    const float* x1b = d_x1 + b*8*POS;
    for (int c=0;c<8;c++){
        #pragma unroll
        for (int di=0;di<3;di++){
            int ii = i+di-1; if (ii<0||ii>=HN) continue;
            #pragma unroll
            for (int dj=0;dj<3;dj++){
                int jj = j+dj-1; if (jj<0||jj>=WN) continue;
                float v = x1b[c*POS + ii*WN + jj];
                unsigned long long vv = pack2(v, v);
                const unsigned long long* wp = sw2p[c*9 + di*3 + dj];
                #pragma unroll
                for (int q=0;q<8;q++) acc2[q] = fma2(vv, wp[q], acc2[q]);
            }
        }
    }
    float q0=bih[0], q1=bih[1], q2=bih[2];
    #pragma unroll
    for (int q=0;q<8;q++){
        float xa, xb;
        unpack2(acc2[q], xa, xb);
        int o = 2*q;
        xa = xa*ssc[o]   + sof[o];
        xb = xb*ssc[o+1] + sof[o+1];
        q0 += swih[0*16+o]*xa + swih[0*16+o+1]*xb;
        q1 += swih[1*16+o]*xa + swih[1*16+o+1]*xb;
        q2 += swih[2*16+o]*xa + swih[2*16+o+1]*xb;
    }
    int node = b*WN + j;
    int base = (i*3)*NTOT + node;
    d_gi[base          ] = q0;
    d_gi[base +   NTOT ] = q1;
    d_gi[base + 2*NTOT ] = q2;
}

// ---------------- GRU: preload ALL 117 gates into registers, then compute ----------------
__global__ void k_gru(const float* __restrict__ maskv,
                      const float* __restrict__ whh, const float* __restrict__ bhh){
    int node = blockIdx.x*64 + threadIdx.x;
    if (node >= NTOT) return;
    float g[3*HN];
    #pragma unroll
    for (int t=0;t<HN;t++){
        int base = (t*3)*NTOT + node;
        g[t*3+0] = d_gi[base];
        g[t*3+1] = d_gi[base + NTOT];
        g[t*3+2] = d_gi[base + 2*NTOT];
    }
    float mk = maskv[node];
    float hw0 = 0.5f*whh[0], hw1 = 0.5f*whh[1], w2 = whh[2];
    float hb0 = 0.5f*bhh[0], hb1 = 0.5f*bhh[1], bh2 = bhh[2];
    float h = 0.f;
    #pragma unroll
    for (int t=0;t<HN;t++){
        float r = 0.5f + 0.5f*fast_tanh(0.5f*g[t*3+0] + hb0 + hw0*h);
        float z = 0.5f + 0.5f*fast_tanh(0.5f*g[t*3+1] + hb1 + hw1*h);
        float n = fast_tanh(g[t*3+2] + r*(w2*h + bh2));
        h = n + z*(h - n);
        d_xnT[(HN+t)*NTOT + node] = h*mk;
    }
}

// ---------------- bucketed CSR scatter (no hist/scan) ----------------
__global__ void k_scatter(const int* __restrict__ eib){
    int e = blockIdx.x*blockDim.x + threadIdx.x;
    if (e >= ET) return;
    int src, dst;
    if (e < E0){ src = eib[e]; dst = eib[E0+e]; }
    else { src = dst = e - E0; }
    int pos = atomicAdd(&d_cur[dst], 1);
    d_csr[dst*CAP + pos] = src;
}

// ---------------- proj layer1: 128n x 64m tile, 256 thr, 8n x 4m per thread, f32x2 ----------------
__global__ void k_proj1(const float* __restrict__ Wl, const float* __restrict__ bl,
                        const float* __restrict__ Wr, const float* __restrict__ br){
    const int K = F1;
    int m0g = blockIdx.x*64;
    bool isR = (m0g >= D1);
    const float* W    = isR ? Wr : Wl;
    const float* bias = isR ? br : bl;
    int m0 = isR ? (m0g - D1) : m0g;
    float* C = isR ? d_xr1 : d_xl1;
    int n0 = blockIdx.y*128;

    __shared__ float As[16][132];               // [k][n]
    __shared__ unsigned long long Wp[16][32];   // [k][m-pair]
    int tid = threadIdx.x;
    int tx = tid & 15, ty = tid >> 4;           // tx -> m (4 each), ty -> n (8 each)

    unsigned long long acc[8][2];
    #pragma unroll
    for (int i=0;i<8;i++){ acc[i][0]=0ull; acc[i][1]=0ull; }

    for (int k0=0; k0<K; k0+=16){
        #pragma unroll
        for (int q=0;q<2;q++){
            int lin = tid + q*256;
            int k = lin >> 5, n4 = (lin & 31)*4;
            float4 v;
            if (k0+k < K) v = *reinterpret_cast<const float4*>(&d_xnT[(k0+k)*NTOT + n0+n4]);
            else          v = make_float4(0.f,0.f,0.f,0.f);
            *reinterpret_cast<float4*>(&As[k][n4]) = v;
        }
        #pragma unroll
        for (int q=0;q<2;q++){
            int lin = tid + q*256;
            int mp = lin & 31, k = lin >> 5;
            float wa = 0.f, wb = 0.f;
            if (k0+k < K){
                wa = W[(m0+2*mp  )*K + k0+k];
                wb = W[(m0+2*mp+1)*K + k0+k];
            }
            Wp[k][mp] = pack2(wa, wb);
        }
        __syncthreads();
        #pragma unroll
        for (int kk=0;kk<16;kk++){
            float4 a0 = *reinterpret_cast<const float4*>(&As[kk][ty*8]);
            float4 a1 = *reinterpret_cast<const float4*>(&As[kk][ty*8+4]);
            ulonglong2 w = *reinterpret_cast<const ulonglong2*>(&Wp[kk][tx*2]);
            unsigned long long ap[8];
            ap[0]=pack2(a0.x,a0.x); ap[1]=pack2(a0.y,a0.y);
            ap[2]=pack2(a0.z,a0.z); ap[3]=pack2(a0.w,a0.w);
            ap[4]=pack2(a1.x,a1.x); ap[5]=pack2(a1.y,a1.y);
            ap[6]=pack2(a1.z,a1.z); ap[7]=pack2(a1.w,a1.w);
            #pragma unroll
            for (int i=0;i<8;i++){
                acc[i][0] = fma2(ap[i], w.x, acc[i][0]);
                acc[i][1] = fma2(ap[i], w.y, acc[i][1]);
            }
        }
        __syncthreads();
    }
    int m = m0 + tx*4;
    float4 bv = *reinterpret_cast<const float4*>(&bias[m]);
    #pragma unroll
    for (int i=0;i<8;i++){
        int n = n0 + ty*8 + i;
        float v0,v1,v2,v3;
        unpack2(acc[i][0], v0, v1);
        unpack2(acc[i][1], v2, v3);
        float4 r4 = make_float4(v0+bv.x, v1+bv.y, v2+bv.z, v3+bv.w);
        *reinterpret_cast<float4*>(&C[n*D1 + m]) = r4;
    }
}

// ---------------- proj layer2: 64x64 tile, 256 thr, 4n x 4m per thread, f32x2 ----------------
__global__ void k_proj2(const float* __restrict__ Wl, const float* __restrict__ bl,
                        const float* __restrict__ Wr, const float* __restrict__ br){
    const int K = D1;
    bool isR = (blockIdx.x != 0);
    const float* W    = isR ? Wr : Wl;
    const float* bias = isR ? br : bl;
    float* C = isR ? d_xr2 : d_xl2;
    int n0 = blockIdx.y*64;

    __shared__ float As[32][64];
    __shared__ unsigned long long Wp[32][32];
    int tid = threadIdx.x;
    int tx = tid & 15, ty = tid >> 4;           // tx -> m (4 each), ty -> n (4 each)

    unsigned long long acc[4][2];
    #pragma unroll
    for (int i=0;i<4;i++){ acc[i][0]=0ull; acc[i][1]=0ull; }

    for (int k0=0; k0<K; k0+=32){
        // A: 64n x 32k floats, 256 thr -> 2 float4 each
        #pragma unroll
        for (int q=0;q<2;q++){
            int lin = tid + q*256;
            int n = lin & 63, kq = (lin >> 6)*4;
            float4 v = *reinterpret_cast<const float4*>(&d_h1[(n0+n)*D1 + k0+kq]);
            As[kq+0][n] = v.x;
            As[kq+1][n] = v.y;
            As[kq+2][n] = v.z;
            As[kq+3][n] = v.w;
        }
        // W pairs: 32 mp x 32 k = 1024, 256 thr -> 4 each
        #pragma unroll
        for (int q=0;q<4;q++){
            int lin = tid + q*256;
            int mp = lin >> 5, k = lin & 31;
            Wp[k][mp] = pack2(W[(2*mp  )*K + k0+k], W[(2*mp+1)*K + k0+k]);
        }
        __syncthreads();
        #pragma unroll
        for (int kk=0;kk<32;kk++){
            float4 a0 = *reinterpret_cast<const float4*>(&As[kk][ty*4]);
            ulonglong2 w01 = *reinterpret_cast<const ulonglong2*>(&Wp[kk][tx*2]);
            unsigned long long ap[4];
            ap[0]=pack2(a0.x,a0.x); ap[1]=pack2(a0.y,a0.y);
            ap[2]=pack2(a0.z,a0.z); ap[3]=pack2(a0.w,a0.w);
            #pragma unroll
            for (int i=0;i<4;i++){
                acc[i][0] = fma2(ap[i], w01.x, acc[i][0]);
                acc[i][1] = fma2(ap[i], w01.y, acc[i][1]);
            }
        }
        __syncthreads();
    }
    int m = tx*4;
    float4 bA = *reinterpret_cast<const float4*>(&bias[m]);
    #pragma unroll
    for (int i=0;i<4;i++){
        int n = n0 + ty*4 + i;
        float v0,v1,v2,v3;
        unpack2(acc[i][0], v0, v1);
        unpack2(acc[i][1], v2, v3);
        float4 r4 = make_float4(v0+bA.x, v1+bA.y, v2+bA.z, v3+bA.w);
        *reinterpret_cast<float4*>(&C[n*OUTC + m]) = r4;
    }
}

// ---------------- GAT1: lrelu folded, unroll 4 (8 outstanding gathers/group) ----------------
__global__ void k_gat1(const float* __restrict__ att, const float* __restrict__ bias){
    int d = blockIdx.x;
    int h = threadIdx.x >> 5, lane = threadIdx.x & 31;
    int g = lane >> 3, l8 = lane & 7;
    int col = h*HID + l8*8;
    const float4* xr4 = reinterpret_cast<const float4*>(&d_xr1[d*D1 + col]);
    float4 xrA = xr4[0], xrB = xr4[1];
    const float4* at4 = reinterpret_cast<const float4*>(&att[col]);
    float4 atA = at4[0], atB = at4[1];
    float4 pA = make_float4(0.6f*atA.x, 0.6f*atA.y, 0.6f*atA.z, 0.6f*atA.w);
    float4 pB = make_float4(0.6f*atB.x, 0.6f*atB.y, 0.6f*atB.z, 0.6f*atB.w);
    float4 rA_ = make_float4(0.4f*atA.x, 0.4f*atA.y, 0.4f*atA.z, 0.4f*atA.w);
    float4 rB_ = make_float4(0.4f*atB.x, 0.4f*atB.y, 0.4f*atB.z, 0.4f*atB.w);

    float den = 0.f;
    float s[8] = {0,0,0,0,0,0,0,0};
    int eb = d*CAP;
    int deg = d_cur[d];
    #pragma unroll 4
    for (int i0 = 0; i0 < deg; i0 += 4){
        int i = i0 + g;
        bool valid = (i < deg);
        int src = d_csr[eb + (valid ? i : 0)];
        const float4* xl4 = reinterpret_cast<const float4*>(&d_xl1[src*D1 + col]);
        float4 lA = xl4[0], lB = xl4[1];
        float t, q = 0.f;
        t = lA.x + xrA.x; q = __fmaf_rn(pA.x, t, __fmaf_rn(rA_.x, fabsf(t), q));
        t = lA.y + xrA.y; q = __fmaf_rn(pA.y, t, __fmaf_rn(rA_.y, fabsf(t), q));
        t = lA.z + xrA.z; q = __fmaf_rn(pA.z, t, __fmaf_rn(rA_.z, fabsf(t), q));
        t = lA.w + xrA.w; q = __fmaf_rn(pA.w, t, __fmaf_rn(rA_.w, fabsf(t), q));
        t = lB.x + xrB.x; q = __fmaf_rn(pB.x, t, __fmaf_rn(rB_.x, fabsf(t), q));
        t = lB.y + xrB.y; q = __fmaf_rn(pB.y, t, __fmaf_rn(rB_.y, fabsf(t), q));
        t = lB.z + xrB.z; q = __fmaf_rn(pB.z, t, __fmaf_rn(rB_.z, fabsf(t), q));
        t = lB.w + xrB.w; q = __fmaf_rn(pB.w, t, __fmaf_rn(rB_.w, fabsf(t), q));
        q += __shfl_xor_sync(0xffffffffu, q, 1);
        q += __shfl_xor_sync(0xffffffffu, q, 2);
        q += __shfl_xor_sync(0xffffffffu, q, 4);
        float wv = valid ? __expf(q) : 0.f;
        den += wv;
        s[0] += wv*lA.x; s[1] += wv*lA.y; s[2] += wv*lA.z; s[3] += wv*lA.w;
        s[4] += wv*lB.x; s[5] += wv*lB.y; s[6] += wv*lB.z; s[7] += wv*lB.w;
    }
    #pragma unroll
    for (int o=8;o<=16;o<<=1){
        den += __shfl_xor_sync(0xffffffffu, den, o);
        #pragma unroll
        for (int k=0;k<8;k++) s[k] += __shfl_xor_sync(0xffffffffu, s[k], o);
    }
    if (g == 0){
        float inv = __fdividef(1.f, den);
        float o0;
        float4 rA, rB;
        o0 = s[0]*inv + bias[col+0]; rA.x = o0>0.f? o0 : (__expf(o0)-1.f);
        o0 = s[1]*inv + bias[col+1]; rA.y = o0>0.f? o0 : (__expf(o0)-1.f);
        o0 = s[2]*inv + bias[col+2]; rA.z = o0>0.f? o0 : (__expf(o0)-1.f);
        o0 = s[3]*inv + bias[col+3]; rA.w = o0>0.f? o0 : (__expf(o0)-1.f);
        o0 = s[4]*inv + bias[col+4]; rB.x = o0>0.f? o0 : (__expf(o0)-1.f);
        o0 = s[5]*inv + bias[col+5]; rB.y = o0>0.f? o0 : (__expf(o0)-1.f);
        o0 = s[6]*inv + bias[col+6]; rB.z = o0>0.f? o0 : (__expf(o0)-1.f);
        o0 = s[7]*inv + bias[col+7]; rB.w = o0>0.f? o0 : (__expf(o0)-1.f);
        float4* dst = reinterpret_cast<float4*>(&d_h1[d*D1 + col]);
        dst[0] = rA; dst[1] = rB;
    }
}

// ---------------- GAT2: warp per dst, lrelu folded, unroll 4 ----------------
__global__ void k_gat2(const float* __restrict__ att, const float* __restrict__ bias,
                       float* __restrict__ out){
    int d = blockIdx.x*8 + (threadIdx.x>>5);
    int lane = threadIdx.x & 31;
    if (d >= NTOT) return;
    int g = lane >> 3, l8 = lane & 7;
    int col = l8*8;
    const float4* xr4 = reinterpret_cast<const float4*>(&d_xr2[d*OUTC + col]);
    float4 xrA = xr4[0], xrB = xr4[1];
    const float4* at4 = reinterpret_cast<const float4*>(&att[col]);
    float4 atA = at4[0], atB = at4[1];
    float4 pA = make_float4(0.6f*atA.x, 0.6f*atA.y, 0.6f*atA.z, 0.6f*atA.w);
    float4 pB = make_float4(0.6f*atB.x, 0.6f*atB.y, 0.6f*atB.z, 0.6f*atB.w);
    float4 rA_ = make_float4(0.4f*atA.x, 0.4f*atA.y, 0.4f*atA.z, 0.4f*atA.w);
    float4 rB_ = make_float4(0.4f*atB.x, 0.4f*atB.y, 0.4f*atB.z, 0.4f*atB.w);

    float den = 0.f;
    float s[8] = {0,0,0,0,0,0,0,0};
    int eb = d*CAP;
    int deg = d_cur[d];
    #pragma unroll 4
    for (int i0 = 0; i0 < deg; i0 += 4){
        int i = i0 + g;
        bool valid = (i < deg);
        int src = d_csr[eb + (valid ? i : 0)];
        const float4* xl4 = reinterpret_cast<const float4*>(&d_xl2[src*OUTC + col]);
        float4 lA = xl4[0], lB = xl4[1];
        float t, q = 0.f;
        t = lA.x + xrA.x; q = __fmaf_rn(pA.x, t, __fmaf_rn(rA_.x, fabsf(t), q));
        t = lA.y + xrA.y; q = __fmaf_rn(pA.y, t, __fmaf_rn(rA_.y, fabsf(t), q));
        t = lA.z + xrA.z; q = __fmaf_rn(pA.z, t, __fmaf_rn(rA_.z, fabsf(t), q));
        t = lA.w + xrA.w; q = __fmaf_rn(pA.w, t, __fmaf_rn(rA_.w, fabsf(t), q));
        t = lB.x + xrB.x; q = __fmaf_rn(pB.x, t, __fmaf_rn(rB_.x, fabsf(t), q));
        t = lB.y + xrB.y; q = __fmaf_rn(pB.y, t, __fmaf_rn(rB_.y, fabsf(t), q));
        t = lB.z + xrB.z; q = __fmaf_rn(pB.z, t, __fmaf_rn(rB_.z, fabsf(t), q));
        t = lB.w + xrB.w; q = __fmaf_rn(pB.w, t, __fmaf_rn(rB_.w, fabsf(t), q));
        q += __shfl_xor_sync(0xffffffffu, q, 1);
        q += __shfl_xor_sync(0xffffffffu, q, 2);
        q += __shfl_xor_sync(0xffffffffu, q, 4);
        float wv = valid ? __expf(q) : 0.f;
        den += wv;
        s[0] += wv*lA.x; s[1] += wv*lA.y; s[2] += wv*lA.z; s[3] += wv*lA.w;
        s[4] += wv*lB.x; s[5] += wv*lB.y; s[6] += wv*lB.z; s[7] += wv*lB.w;
    }
    #pragma unroll
    for (int o=8;o<=16;o<<=1){
        den += __shfl_xor_sync(0xffffffffu, den, o);
        #pragma unroll
        for (int k=0;k<8;k++) s[k] += __shfl_xor_sync(0xffffffffu, s[k], o);
    }
    if (g == 0){
        float inv = __fdividef(1.f, den);
        float4 rA, rB;
        rA.x = s[0]*inv + bias[col+0];
        rA.y = s[1]*inv + bias[col+1];
        rA.z = s[2]*inv + bias[col+2];
        rA.w = s[3]*inv + bias[col+3];
        rB.x = s[4]*inv + bias[col+4];
        rB.y = s[5]*inv + bias[col+5];
        rB.z = s[6]*inv + bias[col+6];
        rB.w = s[7]*inv + bias[col+7];
        float4* dst = reinterpret_cast<float4*>(&out[d*OUTC + col]);
        dst[0] = rA; dst[1] = rB;
    }
}

// ---------------- host launch ----------------
extern "C" void kernel_launch(void* const* d_in, const int* in_sizes, int n_in,
                              void* d_out, int out_size){
    const int*   eib   = (const int*)d_in[0];
    const float* ve    = (const float*)d_in[1];
    const float* ac    = (const float*)d_in[2];
    const float* man   = (const float*)d_in[3];
    const float* mask  = (const float*)d_in[4];
    const float* c1w   = (const float*)d_in[6];
    const float* c1b   = (const float*)d_in[7];
    const float* bn1g  = (const float*)d_in[8];
    const float* bn1b  = (const float*)d_in[9];
    const float* c2w   = (const float*)d_in[10];
    const float* c2b   = (const float*)d_in[11];
    const float* bn2g  = (const float*)d_in[12];
    const float* bn2b  = (const float*)d_in[13];
    const float* gwih  = (const float*)d_in[14];
    const float* gwhh  = (const float*)d_in[15];
    const float* gbih  = (const float*)d_in[16];
    const float* gbhh  = (const float*)d_in[17];
    const float* g1wl  = (const float*)d_in[18];
    const float* g1bl  = (const float*)d_in[19];
    const float* g1wr  = (const float*)d_in[20];
    const float* g1br  = (const float*)d_in[21];
    const float* g1att = (const float*)d_in[22];
    const float* g1bias= (const float*)d_in[23];
    const float* g2wl  = (const float*)d_in[24];
    const float* g2bl  = (const float*)d_in[25];
    const float* g2wr  = (const float*)d_in[26];
    const float* g2br  = (const float*)d_in[27];
    const float* g2att = (const float*)d_in[28];
    const float* g2bias= (const float*)d_in[29];
    float* out = (float*)d_out;

    // conv2 lands in profiled slot 4
    k_conv1<<<(BB*POS+255)/256, 256>>>(man, ac, ve, mask, c1w, c1b, bn1g, bn1b);
    k_init<<<(NTOT+255)/256, 256>>>();
    k_scatter<<<(ET+255)/256, 256>>>(eib);
    k_conv2<<<dim3(BB, (POS+255)/256), 256>>>(c2w, c2b, bn2g, bn2b, gwih, gbih);
    k_gru<<<(NTOT+63)/64, 64>>>(mask, gwhh, gbhh);
    k_proj1<<<dim3(2*D1/64, NTOT/128), 256>>>(g1wl, g1bl, g1wr, g1br);
    k_gat1<<<NTOT, 256>>>(g1att, g1bias);
    k_proj2<<<dim3(2, NTOT/64), 256>>>(g2wl, g2bl, g2wr, g2br);
    k_gat2<<<(NTOT+7)/8, 256>>>(g2att, g2bias, out);
}

// round 14
// speedup vs baseline: 1.0518x; 1.0518x over previous
#include <cuda_runtime.h>
#include <math.h>

#define NTOT 4992
#define BB 128
#define HN 39
#define WN 39
#define POS 1521      // 39*39
#define PW 41         // padded width
#define PPOS 1681     // 41*41
#define E0 200064     // B*E_PER
#define ET 205056     // E0 + NTOT self loops
#define HEADS 8
#define HID 64
#define OUTC 64
#define F1 78
#define D1 512
#define CAP 128       // per-dst CSR bucket capacity

// ---------------- scratch (static device memory; no allocation) ----------------
__device__ float d_x1p[BB*8*PPOS];    // conv1 output, zero-padded (B,8,41,41); borders never written
__device__ float d_gi[3*HN*NTOT];
__device__ float d_xnT[F1*NTOT];
__device__ __align__(2048) float d_xl1[NTOT*D1];
__device__ float d_xr1[NTOT*D1];
__device__ float d_h1[NTOT*D1];
__device__ float d_xl2[NTOT*OUTC];
__device__ float d_xr2[NTOT*OUTC];
__device__ int   d_cur[NTOT];
__device__ int   d_csr[NTOT*CAP];

__device__ __forceinline__ float nz(float v){ return isnan(v) ? 0.0f : v; }
__device__ __forceinline__ float fast_tanh(float x){
    float r; asm("tanh.approx.f32 %0, %1;" : "=f"(r) : "f"(x)); return r;
}

// ------ f32x2 packed math helpers ------
__device__ __forceinline__ unsigned long long pack2(float lo, float hi){
    unsigned long long r;
    asm("mov.b64 %0, {%1,%2};" : "=l"(r) : "f"(lo), "f"(hi));
    return r;
}
__device__ __forceinline__ unsigned long long fma2(unsigned long long a,
                                                   unsigned long long b,
                                                   unsigned long long c){
    unsigned long long d;
    asm("fma.rn.f32x2 %0, %1, %2, %3;" : "=l"(d) : "l"(a), "l"(b), "l"(c));
    return d;
}
__device__ __forceinline__ void unpack2(unsigned long long v, float& lo, float& hi){
    asm("mov.b64 {%0,%1}, %2;" : "=f"(lo), "=f"(hi) : "l"(v));
}

// ---------------- init: zero bucket counters ----------------
__global__ void k_init(){
    int i = blockIdx.x*blockDim.x + threadIdx.x;
    if (i < NTOT) d_cur[i] = 0;
}

// ---------------- conv1 (1x1, 3->8) + BN + ReLU -> padded layout; fused man copy ----------------
__global__ void k_conv1(const float* __restrict__ man, const float* __restrict__ ac,
                        const float* __restrict__ ve, const float* __restrict__ maskv,
                        const float* __restrict__ w1, const float* __restrict__ b1,
                        const float* __restrict__ g1, const float* __restrict__ bb1){
    int idx = blockIdx.x*blockDim.x + threadIdx.x;
    if (idx >= BB*POS) return;
    int b = idx / POS, p = idx % POS;
    float c0 = nz(man[idx]), c1 = nz(ac[idx]), c2 = nz(ve[idx]);
    int f = p / WN, j = p % WN;
    int node = b*WN + j;
    d_xnT[f*NTOT + node] = c0 * maskv[node];
    const float inv = rsqrtf(1.0f + 1e-5f);
    int pp = (f+1)*PW + (j+1);        // interior of padded tile
    #pragma unroll
    for (int o=0;o<8;o++){
        float v = w1[o*3+0]*c0 + w1[o*3+1]*c1 + w1[o*3+2]*c2 + b1[o];
        v = v * (g1[o]*inv) + bb1[o];
        d_x1p[(b*8+o)*PPOS + pp] = fmaxf(v, 0.0f);
    }
}

// ---------------- conv2 (3x3, 8->16, padded input) + BN + GRU input projection ----------------
__global__ void k_conv2(const float* __restrict__ w2, const float* __restrict__ b2,
                        const float* __restrict__ g2, const float* __restrict__ bb2,
                        const float* __restrict__ wih, const float* __restrict__ bih){
    __shared__ unsigned long long sw2p[72][8];
    __shared__ float ssc[16], sof[16];
    __shared__ float swih[48];
    int tid = threadIdx.x;
    for (int i=tid;i<576;i+=blockDim.x){
        int tap = i>>3, op = i&7;
        sw2p[tap][op] = pack2(w2[(2*op)*72+tap], w2[(2*op+1)*72+tap]);
    }
    if (tid<16){ float s = g2[tid]*rsqrtf(1.0f+1e-5f); ssc[tid]=s; sof[tid]=b2[tid]*s + bb2[tid]; }
    if (tid<48) swih[tid]=wih[tid];
    __syncthreads();
    int b = blockIdx.x;
    int p = blockIdx.y*blockDim.x + tid;
    if (p >= POS) return;
    int i = p / WN, j = p % WN;
    unsigned long long acc2[8] = {0ull,0ull,0ull,0ull,0ull,0ull,0ull,0ull};
    // top-left of 3x3 window in padded coords = (i, j) .. (i+2, j+2)
    const float* x1b = d_x1p + b*8*PPOS + i*PW + j;
    #pragma unroll
    for (int c=0;c<8;c++){
        #pragma unroll
        for (int di=0;di<3;di++){
            #pragma unroll
            for (int dj=0;dj<3;dj++){
                float v = x1b[c*PPOS + di*PW + dj];   // constant offset per tap
                unsigned long long vv = pack2(v, v);
                const unsigned long long* wp = sw2p[c*9 + di*3 + dj];
                #pragma unroll
                for (int q=0;q<8;q++) acc2[q] = fma2(vv, wp[q], acc2[q]);
            }
        }
    }
    float q0=bih[0], q1=bih[1], q2=bih[2];
    #pragma unroll
    for (int q=0;q<8;q++){
        float xa, xb;
        unpack2(acc2[q], xa, xb);
        int o = 2*q;
        xa = xa*ssc[o]   + sof[o];
        xb = xb*ssc[o+1] + sof[o+1];
        q0 += swih[0*16+o]*xa + swih[0*16+o+1]*xb;
        q1 += swih[1*16+o]*xa + swih[1*16+o+1]*xb;
        q2 += swih[2*16+o]*xa + swih[2*16+o+1]*xb;
    }
    int node = b*WN + j;
    int base = (i*3)*NTOT + node;
    d_gi[base          ] = q0;
    d_gi[base +   NTOT ] = q1;
    d_gi[base + 2*NTOT ] = q2;
}

// ---------------- GRU: preload ALL 117 gates into registers, then compute ----------------
__global__ void k_gru(const float* __restrict__ maskv,
                      const float* __restrict__ whh, const float* __restrict__ bhh){
    int node = blockIdx.x*64 + threadIdx.x;
    if (node >= NTOT) return;
    float g[3*HN];
    #pragma unroll
    for (int t=0;t<HN;t++){
        int base = (t*3)*NTOT + node;
        g[t*3+0] = d_gi[base];
        g[t*3+1] = d_gi[base + NTOT];
        g[t*3+2] = d_gi[base + 2*NTOT];
    }
    float mk = maskv[node];
    float hw0 = 0.5f*whh[0], hw1 = 0.5f*whh[1], w2 = whh[2];
    float hb0 = 0.5f*bhh[0], hb1 = 0.5f*bhh[1], bh2 = bhh[2];
    float h = 0.f;
    #pragma unroll
    for (int t=0;t<HN;t++){
        float r = 0.5f + 0.5f*fast_tanh(0.5f*g[t*3+0] + hb0 + hw0*h);
        float z = 0.5f + 0.5f*fast_tanh(0.5f*g[t*3+1] + hb1 + hw1*h);
        float n = fast_tanh(g[t*3+2] + r*(w2*h + bh2));
        h = n + z*(h - n);
        d_xnT[(HN+t)*NTOT + node] = h*mk;
    }
}

// ---------------- bucketed CSR scatter ----------------
__global__ void k_scatter(const int* __restrict__ eib){
    int e = blockIdx.x*blockDim.x + threadIdx.x;
    if (e >= ET) return;
    int src, dst;
    if (e < E0){ src = eib[e]; dst = eib[E0+e]; }
    else { src = dst = e - E0; }
    int pos = atomicAdd(&d_cur[dst], 1);
    d_csr[dst*CAP + pos] = src;
}

// ---------------- proj layer1: 128n x 64m tile, 256 thr, 8n x 4m per thread, f32x2 ----------------
__global__ void k_proj1(const float* __restrict__ Wl, const float* __restrict__ bl,
                        const float* __restrict__ Wr, const float* __restrict__ br){
    const int K = F1;
    int m0g = blockIdx.x*64;
    bool isR = (m0g >= D1);
    const float* W    = isR ? Wr : Wl;
    const float* bias = isR ? br : bl;
    int m0 = isR ? (m0g - D1) : m0g;
    float* C = isR ? d_xr1 : d_xl1;
    int n0 = blockIdx.y*128;

    __shared__ float As[16][132];
    __shared__ unsigned long long Wp[16][32];
    int tid = threadIdx.x;
    int tx = tid & 15, ty = tid >> 4;

    unsigned long long acc[8][2];
    #pragma unroll
    for (int i=0;i<8;i++){ acc[i][0]=0ull; acc[i][1]=0ull; }

    for (int k0=0; k0<K; k0+=16){
        #pragma unroll
        for (int q=0;q<2;q++){
            int lin = tid + q*256;
            int k = lin >> 5, n4 = (lin & 31)*4;
            float4 v;
            if (k0+k < K) v = *reinterpret_cast<const float4*>(&d_xnT[(k0+k)*NTOT + n0+n4]);
            else          v = make_float4(0.f,0.f,0.f,0.f);
            *reinterpret_cast<float4*>(&As[k][n4]) = v;
        }
        #pragma unroll
        for (int q=0;q<2;q++){
            int lin = tid + q*256;
            int mp = lin & 31, k = lin >> 5;
            float wa = 0.f, wb = 0.f;
            if (k0+k < K){
                wa = W[(m0+2*mp  )*K + k0+k];
                wb = W[(m0+2*mp+1)*K + k0+k];
            }
            Wp[k][mp] = pack2(wa, wb);
        }
        __syncthreads();
        #pragma unroll
        for (int kk=0;kk<16;kk++){
            float4 a0 = *reinterpret_cast<const float4*>(&As[kk][ty*8]);
            float4 a1 = *reinterpret_cast<const float4*>(&As[kk][ty*8+4]);
            ulonglong2 w = *reinterpret_cast<const ulonglong2*>(&Wp[kk][tx*2]);
            unsigned long long ap[8];
            ap[0]=pack2(a0.x,a0.x); ap[1]=pack2(a0.y,a0.y);
            ap[2]=pack2(a0.z,a0.z); ap[3]=pack2(a0.w,a0.w);
            ap[4]=pack2(a1.x,a1.x); ap[5]=pack2(a1.y,a1.y);
            ap[6]=pack2(a1.z,a1.z); ap[7]=pack2(a1.w,a1.w);
            #pragma unroll
            for (int i=0;i<8;i++){
                acc[i][0] = fma2(ap[i], w.x, acc[i][0]);
                acc[i][1] = fma2(ap[i], w.y, acc[i][1]);
            }
        }
        __syncthreads();
    }
    int m = m0 + tx*4;
    float4 bv = *reinterpret_cast<const float4*>(&bias[m]);
    #pragma unroll
    for (int i=0;i<8;i++){
        int n = n0 + ty*8 + i;
        float v0,v1,v2,v3;
        unpack2(acc[i][0], v0, v1);
        unpack2(acc[i][1], v2, v3);
        float4 r4 = make_float4(v0+bv.x, v1+bv.y, v2+bv.z, v3+bv.w);
        *reinterpret_cast<float4*>(&C[n*D1 + m]) = r4;
    }
}

// ---------------- proj layer2: 64x64 tile, 256 thr, 4n x 4m per thread, f32x2 ----------------
__global__ void k_proj2(const float* __restrict__ Wl, const float* __restrict__ bl,
                        const float* __restrict__ Wr, const float* __restrict__ br){
    const int K = D1;
    bool isR = (blockIdx.x != 0);
    const float* W    = isR ? Wr : Wl;
    const float* bias = isR ? br : bl;
    float* C = isR ? d_xr2 : d_xl2;
    int n0 = blockIdx.y*64;

    __shared__ float As[32][64];
    __shared__ unsigned long long Wp[32][32];
    int tid = threadIdx.x;
    int tx = tid & 15, ty = tid >> 4;

    unsigned long long acc[4][2];
    #pragma unroll
    for (int i=0;i<4;i++){ acc[i][0]=0ull; acc[i][1]=0ull; }

    for (int k0=0; k0<K; k0+=32){
        #pragma unroll
        for (int q=0;q<2;q++){
            int lin = tid + q*256;
            int n = lin & 63, kq = (lin >> 6)*4;
            float4 v = *reinterpret_cast<const float4*>(&d_h1[(n0+n)*D1 + k0+kq]);
            As[kq+0][n] = v.x;
            As[kq+1][n] = v.y;
            As[kq+2][n] = v.z;
            As[kq+3][n] = v.w;
        }
        #pragma unroll
        for (int q=0;q<4;q++){
            int lin = tid + q*256;
            int mp = lin >> 5, k = lin & 31;
            Wp[k][mp] = pack2(W[(2*mp  )*K + k0+k], W[(2*mp+1)*K + k0+k]);
        }
        __syncthreads();
        #pragma unroll
        for (int kk=0;kk<32;kk++){
            float4 a0 = *reinterpret_cast<const float4*>(&As[kk][ty*4]);
            ulonglong2 w01 = *reinterpret_cast<const ulonglong2*>(&Wp[kk][tx*2]);
            unsigned long long ap[4];
            ap[0]=pack2(a0.x,a0.x); ap[1]=pack2(a0.y,a0.y);
            ap[2]=pack2(a0.z,a0.z); ap[3]=pack2(a0.w,a0.w);
            #pragma unroll
            for (int i=0;i<4;i++){
                acc[i][0] = fma2(ap[i], w01.x, acc[i][0]);
                acc[i][1] = fma2(ap[i], w01.y, acc[i][1]);
            }
        }
        __syncthreads();
    }
    int m = tx*4;
    float4 bA = *reinterpret_cast<const float4*>(&bias[m]);
    #pragma unroll
    for (int i=0;i<4;i++){
        int n = n0 + ty*4 + i;
        float v0,v1,v2,v3;
        unpack2(acc[i][0], v0, v1);
        unpack2(acc[i][1], v2, v3);
        float4 r4 = make_float4(v0+bA.x, v1+bA.y, v2+bA.z, v3+bA.w);
        *reinterpret_cast<float4*>(&C[n*OUTC + m]) = r4;
    }
}

// ---------------- GAT1: lrelu folded, unroll 2 ----------------
__global__ void k_gat1(const float* __restrict__ att, const float* __restrict__ bias){
    int d = blockIdx.x;
    int h = threadIdx.x >> 5, lane = threadIdx.x & 31;
    int g = lane >> 3, l8 = lane & 7;
    int col = h*HID + l8*8;
    const float4* xr4 = reinterpret_cast<const float4*>(&d_xr1[d*D1 + col]);
    float4 xrA = xr4[0], xrB = xr4[1];
    const float4* at4 = reinterpret_cast<const float4*>(&att[col]);
    float4 atA = at4[0], atB = at4[1];
    float4 pA = make_float4(0.6f*atA.x, 0.6f*atA.y, 0.6f*atA.z, 0.6f*atA.w);
    float4 pB = make_float4(0.6f*atB.x, 0.6f*atB.y, 0.6f*atB.z, 0.6f*atB.w);
    float4 rA_ = make_float4(0.4f*atA.x, 0.4f*atA.y, 0.4f*atA.z, 0.4f*atA.w);
    float4 rB_ = make_float4(0.4f*atB.x, 0.4f*atB.y, 0.4f*atB.z, 0.4f*atB.w);

    float den = 0.f;
    float s[8] = {0,0,0,0,0,0,0,0};
    int eb = d*CAP;
    int deg = d_cur[d];
    #pragma unroll 2
    for (int i0 = 0; i0 < deg; i0 += 4){
        int i = i0 + g;
        bool valid = (i < deg);
        int src = d_csr[eb + (valid ? i : 0)];
        const float4* xl4 = reinterpret_cast<const float4*>(&d_xl1[src*D1 + col]);
        float4 lA = xl4[0], lB = xl4[1];
        float t, q = 0.f;
        t = lA.x + xrA.x; q = __fmaf_rn(pA.x, t, __fmaf_rn(rA_.x, fabsf(t), q));
        t = lA.y + xrA.y; q = __fmaf_rn(pA.y, t, __fmaf_rn(rA_.y, fabsf(t), q));
        t = lA.z + xrA.z; q = __fmaf_rn(pA.z, t, __fmaf_rn(rA_.z, fabsf(t), q));
        t = lA.w + xrA.w; q = __fmaf_rn(pA.w, t, __fmaf_rn(rA_.w, fabsf(t), q));
        t = lB.x + xrB.x; q = __fmaf_rn(pB.x, t, __fmaf_rn(rB_.x, fabsf(t), q));
        t = lB.y + xrB.y; q = __fmaf_rn(pB.y, t, __fmaf_rn(rB_.y, fabsf(t), q));
        t = lB.z + xrB.z; q = __fmaf_rn(pB.z, t, __fmaf_rn(rB_.z, fabsf(t), q));
        t = lB.w + xrB.w; q = __fmaf_rn(pB.w, t, __fmaf_rn(rB_.w, fabsf(t), q));
        q += __shfl_xor_sync(0xffffffffu, q, 1);
        q += __shfl_xor_sync(0xffffffffu, q, 2);
        q += __shfl_xor_sync(0xffffffffu, q, 4);
        float wv = valid ? __expf(q) : 0.f;
        den += wv;
        s[0] += wv*lA.x; s[1] += wv*lA.y; s[2] += wv*lA.z; s[3] += wv*lA.w;
        s[4] += wv*lB.x; s[5] += wv*lB.y; s[6] += wv*lB.z; s[7] += wv*lB.w;
    }
    #pragma unroll
    for (int o=8;o<=16;o<<=1){
        den += __shfl_xor_sync(0xffffffffu, den, o);
        #pragma unroll
        for (int k=0;k<8;k++) s[k] += __shfl_xor_sync(0xffffffffu, s[k], o);
    }
    if (g == 0){
        float inv = __fdividef(1.f, den);
        float o0;
        float4 rA, rB;
        o0 = s[0]*inv + bias[col+0]; rA.x = o0>0.f? o0 : (__expf(o0)-1.f);
        o0 = s[1]*inv + bias[col+1]; rA.y = o0>0.f? o0 : (__expf(o0)-1.f);
        o0 = s[2]*inv + bias[col+2]; rA.z = o0>0.f? o0 : (__expf(o0)-1.f);
        o0 = s[3]*inv + bias[col+3]; rA.w = o0>0.f? o0 : (__expf(o0)-1.f);
        o0 = s[4]*inv + bias[col+4]; rB.x = o0>0.f? o0 : (__expf(o0)-1.f);
        o0 = s[5]*inv + bias[col+5]; rB.y = o0>0.f? o0 : (__expf(o0)-1.f);
        o0 = s[6]*inv + bias[col+6]; rB.z = o0>0.f? o0 : (__expf(o0)-1.f);
        o0 = s[7]*inv + bias[col+7]; rB.w = o0>0.f? o0 : (__expf(o0)-1.f);
        float4* dst = reinterpret_cast<float4*>(&d_h1[d*D1 + col]);
        dst[0] = rA; dst[1] = rB;
    }
}

// ---------------- GAT2: warp per dst, lrelu folded, unroll 2 ----------------
__global__ void k_gat2(const float* __restrict__ att, const float* __restrict__ bias,
                       float* __restrict__ out){
    int d = blockIdx.x*8 + (threadIdx.x>>5);
    int lane = threadIdx.x & 31;
    if (d >= NTOT) return;
    int g = lane >> 3, l8 = lane & 7;
    int col = l8*8;
    const float4* xr4 = reinterpret_cast<const float4*>(&d_xr2[d*OUTC + col]);
    float4 xrA = xr4[0], xrB = xr4[1];
    const float4* at4 = reinterpret_cast<const float4*>(&att[col]);
    float4 atA = at4[0], atB = at4[1];
    float4 pA = make_float4(0.6f*atA.x, 0.6f*atA.y, 0.6f*atA.z, 0.6f*atA.w);
    float4 pB = make_float4(0.6f*atB.x, 0.6f*atB.y, 0.6f*atB.z, 0.6f*atB.w);
    float4 rA_ = make_float4(0.4f*atA.x, 0.4f*atA.y, 0.4f*atA.z, 0.4f*atA.w);
    float4 rB_ = make_float4(0.4f*atB.x, 0.4f*atB.y, 0.4f*atB.z, 0.4f*atB.w);

    float den = 0.f;
    float s[8] = {0,0,0,0,0,0,0,0};
    int eb = d*CAP;
    int deg = d_cur[d];
    #pragma unroll 2
    for (int i0 = 0; i0 < deg; i0 += 4){
        int i = i0 + g;
        bool valid = (i < deg);
        int src = d_csr[eb + (valid ? i : 0)];
        const float4* xl4 = reinterpret_cast<const float4*>(&d_xl2[src*OUTC + col]);
        float4 lA = xl4[0], lB = xl4[1];
        float t, q = 0.f;
        t = lA.x + xrA.x; q = __fmaf_rn(pA.x, t, __fmaf_rn(rA_.x, fabsf(t), q));
        t = lA.y + xrA.y; q = __fmaf_rn(pA.y, t, __fmaf_rn(rA_.y, fabsf(t), q));
        t = lA.z + xrA.z; q = __fmaf_rn(pA.z, t, __fmaf_rn(rA_.z, fabsf(t), q));
        t = lA.w + xrA.w; q = __fmaf_rn(pA.w, t, __fmaf_rn(rA_.w, fabsf(t), q));
        t = lB.x + xrB.x; q = __fmaf_rn(pB.x, t, __fmaf_rn(rB_.x, fabsf(t), q));
        t = lB.y + xrB.y; q = __fmaf_rn(pB.y, t, __fmaf_rn(rB_.y, fabsf(t), q));
        t = lB.z + xrB.z; q = __fmaf_rn(pB.z, t, __fmaf_rn(rB_.z, fabsf(t), q));
        t = lB.w + xrB.w; q = __fmaf_rn(pB.w, t, __fmaf_rn(rB_.w, fabsf(t), q));
        q += __shfl_xor_sync(0xffffffffu, q, 1);
        q += __shfl_xor_sync(0xffffffffu, q, 2);
        q += __shfl_xor_sync(0xffffffffu, q, 4);
        float wv = valid ? __expf(q) : 0.f;
        den += wv;
        s[0] += wv*lA.x; s[1] += wv*lA.y; s[2] += wv*lA.z; s[3] += wv*lA.w;
        s[4] += wv*lB.x; s[5] += wv*lB.y; s[6] += wv*lB.z; s[7] += wv*lB.w;
    }
    #pragma unroll
    for (int o=8;o<=16;o<<=1){
        den += __shfl_xor_sync(0xffffffffu, den, o);
        #pragma unroll
        for (int k=0;k<8;k++) s[k] += __shfl_xor_sync(0xffffffffu, s[k], o);
    }
    if (g == 0){
        float inv = __fdividef(1.f, den);
        float4 rA, rB;
        rA.x = s[0]*inv + bias[col+0];
        rA.y = s[1]*inv + bias[col+1];
        rA.z = s[2]*inv + bias[col+2];
        rA.w = s[3]*inv + bias[col+3];
        rB.x = s[4]*inv + bias[col+4];
        rB.y = s[5]*inv + bias[col+5];
        rB.z = s[6]*inv + bias[col+6];
        rB.w = s[7]*inv + bias[col+7];
        float4* dst = reinterpret_cast<float4*>(&out[d*OUTC + col]);
        dst[0] = rA; dst[1] = rB;
    }
}

// ---------------- host launch ----------------
extern "C" void kernel_launch(void* const* d_in, const int* in_sizes, int n_in,
                              void* d_out, int out_size){
    const int*   eib   = (const int*)d_in[0];
    const float* ve    = (const float*)d_in[1];
    const float* ac    = (const float*)d_in[2];
    const float* man   = (const float*)d_in[3];
    const float* mask  = (const float*)d_in[4];
    const float* c1w   = (const float*)d_in[6];
    const float* c1b   = (const float*)d_in[7];
    const float* bn1g  = (const float*)d_in[8];
    const float* bn1b  = (const float*)d_in[9];
    const float* c2w   = (const float*)d_in[10];
    const float* c2b   = (const float*)d_in[11];
    const float* bn2g  = (const float*)d_in[12];
    const float* bn2b  = (const float*)d_in[13];
    const float* gwih  = (const float*)d_in[14];
    const float* gwhh  = (const float*)d_in[15];
    const float* gbih  = (const float*)d_in[16];
    const float* gbhh  = (const float*)d_in[17];
    const float* g1wl  = (const float*)d_in[18];
    const float* g1bl  = (const float*)d_in[19];
    const float* g1wr  = (const float*)d_in[20];
    const float* g1br  = (const float*)d_in[21];
    const float* g1att = (const float*)d_in[22];
    const float* g1bias= (const float*)d_in[23];
    const float* g2wl  = (const float*)d_in[24];
    const float* g2bl  = (const float*)d_in[25];
    const float* g2wr  = (const float*)d_in[26];
    const float* g2br  = (const float*)d_in[27];
    const float* g2att = (const float*)d_in[28];
    const float* g2bias= (const float*)d_in[29];
    float* out = (float*)d_out;

    // conv2 in profiled slot 4
    k_conv1<<<(BB*POS+255)/256, 256>>>(man, ac, ve, mask, c1w, c1b, bn1g, bn1b);
    k_init<<<(NTOT+255)/256, 256>>>();
    k_scatter<<<(ET+255)/256, 256>>>(eib);
    k_conv2<<<dim3(BB, (POS+255)/256), 256>>>(c2w, c2b, bn2g, bn2b, gwih, gbih);
    k_gru<<<(NTOT+63)/64, 64>>>(mask, gwhh, gbhh);
    k_proj1<<<dim3(2*D1/64, NTOT/128), 256>>>(g1wl, g1bl, g1wr, g1br);
    k_gat1<<<NTOT, 256>>>(g1att, g1bias);
    k_proj2<<<dim3(2, NTOT/64), 256>>>(g2wl, g2bl, g2wr, g2br);
    k_gat2<<<(NTOT+7)/8, 256>>>(g2att, g2bias, out);
}

// round 15
// speedup vs baseline: 1.1378x; 1.0818x over previous
#include <cuda_runtime.h>
#include <math.h>

#define NTOT 4992
#define BB 128
#define HN 39
#define WN 39
#define POS 1521      // 39*39
#define PW 41         // padded width
#define PPOS 1681     // 41*41
#define JP 20         // j-pairs per row (2 px/thread)
#define POS2 780      // 39*20
#define E0 200064     // B*E_PER
#define ET 205056     // E0 + NTOT self loops
#define HEADS 8
#define HID 64
#define OUTC 64
#define F1 78
#define D1 512
#define CAP 128       // per-dst CSR bucket capacity

// ---------------- scratch (static device memory; no allocation) ----------------
__device__ float d_x1p[BB*8*PPOS];    // conv1 output, zero-padded (B,8,41,41)
__device__ float d_gi[3*HN*NTOT];
__device__ float d_xnT[F1*NTOT];
__device__ __align__(2048) float d_xl1[NTOT*D1];
__device__ float d_xr1[NTOT*D1];
__device__ float d_h1[NTOT*D1];
__device__ float d_xl2[NTOT*OUTC];
__device__ float d_xr2[NTOT*OUTC];
__device__ int   d_cur[NTOT];
__device__ int   d_csr[NTOT*CAP];

__device__ __forceinline__ float nz(float v){ return isnan(v) ? 0.0f : v; }
__device__ __forceinline__ float fast_tanh(float x){
    float r; asm("tanh.approx.f32 %0, %1;" : "=f"(r) : "f"(x)); return r;
}

// ------ f32x2 packed math helpers ------
__device__ __forceinline__ unsigned long long pack2(float lo, float hi){
    unsigned long long r;
    asm("mov.b64 %0, {%1,%2};" : "=l"(r) : "f"(lo), "f"(hi));
    return r;
}
__device__ __forceinline__ unsigned long long fma2(unsigned long long a,
                                                   unsigned long long b,
                                                   unsigned long long c){
    unsigned long long d;
    asm("fma.rn.f32x2 %0, %1, %2, %3;" : "=l"(d) : "l"(a), "l"(b), "l"(c));
    return d;
}
__device__ __forceinline__ void unpack2(unsigned long long v, float& lo, float& hi){
    asm("mov.b64 {%0,%1}, %2;" : "=f"(lo), "=f"(hi) : "l"(v));
}

// ---------------- init: zero bucket counters ----------------
__global__ void k_init(){
    int i = blockIdx.x*blockDim.x + threadIdx.x;
    if (i < NTOT) d_cur[i] = 0;
}

// ---------------- conv1 (1x1, 3->8) + BN + ReLU -> padded layout; fused man copy ----------------
__global__ void k_conv1(const float* __restrict__ man, const float* __restrict__ ac,
                        const float* __restrict__ ve, const float* __restrict__ maskv,
                        const float* __restrict__ w1, const float* __restrict__ b1,
                        const float* __restrict__ g1, const float* __restrict__ bb1){
    int idx = blockIdx.x*blockDim.x + threadIdx.x;
    if (idx >= BB*POS) return;
    int b = idx / POS, p = idx % POS;
    float c0 = nz(man[idx]), c1 = nz(ac[idx]), c2 = nz(ve[idx]);
    int f = p / WN, j = p % WN;
    int node = b*WN + j;
    d_xnT[f*NTOT + node] = c0 * maskv[node];
    const float inv = rsqrtf(1.0f + 1e-5f);
    int pp = (f+1)*PW + (j+1);
    #pragma unroll
    for (int o=0;o<8;o++){
        float v = w1[o*3+0]*c0 + w1[o*3+1]*c1 + w1[o*3+2]*c2 + b1[o];
        v = v * (g1[o]*inv) + bb1[o];
        d_x1p[(b*8+o)*PPOS + pp] = fmaxf(v, 0.0f);
    }
}

// ---------------- conv2 (3x3, 8->16, padded) + BN + GRU proj; 2 pixels/thread ----------------
__global__ void k_conv2(const float* __restrict__ w2, const float* __restrict__ b2,
                        const float* __restrict__ g2, const float* __restrict__ bb2,
                        const float* __restrict__ wih, const float* __restrict__ bih){
    __shared__ unsigned long long sw2p[72][8];
    __shared__ float ssc[16], sof[16];
    __shared__ float swih[48];
    int tid = threadIdx.x;
    for (int i=tid;i<576;i+=blockDim.x){
        int tap = i>>3, op = i&7;
        sw2p[tap][op] = pack2(w2[(2*op)*72+tap], w2[(2*op+1)*72+tap]);
    }
    if (tid<16){ float s = g2[tid]*rsqrtf(1.0f+1e-5f); ssc[tid]=s; sof[tid]=b2[tid]*s + bb2[tid]; }
    if (tid<48) swih[tid]=wih[tid];
    __syncthreads();
    int b = blockIdx.x;
    int q = blockIdx.y*blockDim.x + tid;
    if (q >= POS2) return;
    int i = q / JP, jp = q % JP;
    int j0 = jp*2;
    bool two = (j0+1 < WN);
    unsigned long long accA[8] = {0ull,0ull,0ull,0ull,0ull,0ull,0ull,0ull};
    unsigned long long accB[8] = {0ull,0ull,0ull,0ull,0ull,0ull,0ull,0ull};
    const float* x1b = d_x1p + b*8*PPOS + i*PW + j0;
    #pragma unroll
    for (int c=0;c<8;c++){
        #pragma unroll
        for (int di=0;di<3;di++){
            const float* row = x1b + c*PPOS + di*PW;
            float v0 = row[0], v1 = row[1], v2 = row[2], v3 = row[3];
            const unsigned long long* wp = sw2p[c*9 + di*3];
            unsigned long long p0 = pack2(v0, v0), p1 = pack2(v1, v1);
            unsigned long long p2 = pack2(v2, v2), p3 = pack2(v3, v3);
            #pragma unroll
            for (int qd=0;qd<8;qd++){
                accA[qd] = fma2(p0, wp[qd], accA[qd]);
                accA[qd] = fma2(p1, wp[8+qd], accA[qd]);
                accA[qd] = fma2(p2, wp[16+qd], accA[qd]);
                accB[qd] = fma2(p1, wp[qd], accB[qd]);
                accB[qd] = fma2(p2, wp[8+qd], accB[qd]);
                accB[qd] = fma2(p3, wp[16+qd], accB[qd]);
            }
        }
    }
    // epilogue pixel A
    {
        float q0=bih[0], q1=bih[1], q2=bih[2];
        #pragma unroll
        for (int qd=0;qd<8;qd++){
            float xa, xb;
            unpack2(accA[qd], xa, xb);
            int o = 2*qd;
            xa = xa*ssc[o]   + sof[o];
            xb = xb*ssc[o+1] + sof[o+1];
            q0 += swih[0*16+o]*xa + swih[0*16+o+1]*xb;
            q1 += swih[1*16+o]*xa + swih[1*16+o+1]*xb;
            q2 += swih[2*16+o]*xa + swih[2*16+o+1]*xb;
        }
        int node = b*WN + j0;
        int base = (i*3)*NTOT + node;
        d_gi[base] = q0; d_gi[base+NTOT] = q1; d_gi[base+2*NTOT] = q2;
    }
    // epilogue pixel B
    if (two){
        float q0=bih[0], q1=bih[1], q2=bih[2];
        #pragma unroll
        for (int qd=0;qd<8;qd++){
            float xa, xb;
            unpack2(accB[qd], xa, xb);
            int o = 2*qd;
            xa = xa*ssc[o]   + sof[o];
            xb = xb*ssc[o+1] + sof[o+1];
            q0 += swih[0*16+o]*xa + swih[0*16+o+1]*xb;
            q1 += swih[1*16+o]*xa + swih[1*16+o+1]*xb;
            q2 += swih[2*16+o]*xa + swih[2*16+o+1]*xb;
        }
        int node = b*WN + j0 + 1;
        int base = (i*3)*NTOT + node;
        d_gi[base] = q0; d_gi[base+NTOT] = q1; d_gi[base+2*NTOT] = q2;
    }
}

// ---------------- GRU: preload ALL 117 gates into registers, then compute ----------------
__global__ void k_gru(const float* __restrict__ maskv,
                      const float* __restrict__ whh, const float* __restrict__ bhh){
    int node = blockIdx.x*64 + threadIdx.x;
    if (node >= NTOT) return;
    float g[3*HN];
    #pragma unroll
    for (int t=0;t<HN;t++){
        int base = (t*3)*NTOT + node;
        g[t*3+0] = d_gi[base];
        g[t*3+1] = d_gi[base + NTOT];
        g[t*3+2] = d_gi[base + 2*NTOT];
    }
    float mk = maskv[node];
    float hw0 = 0.5f*whh[0], hw1 = 0.5f*whh[1], w2 = whh[2];
    float hb0 = 0.5f*bhh[0], hb1 = 0.5f*bhh[1], bh2 = bhh[2];
    float h = 0.f;
    #pragma unroll
    for (int t=0;t<HN;t++){
        float r = 0.5f + 0.5f*fast_tanh(0.5f*g[t*3+0] + hb0 + hw0*h);
        float z = 0.5f + 0.5f*fast_tanh(0.5f*g[t*3+1] + hb1 + hw1*h);
        float n = fast_tanh(g[t*3+2] + r*(w2*h + bh2));
        h = n + z*(h - n);
        d_xnT[(HN+t)*NTOT + node] = h*mk;
    }
}

// ---------------- bucketed CSR scatter ----------------
__global__ void k_scatter(const int* __restrict__ eib){
    int e = blockIdx.x*blockDim.x + threadIdx.x;
    if (e >= ET) return;
    int src, dst;
    if (e < E0){ src = eib[e]; dst = eib[E0+e]; }
    else { src = dst = e - E0; }
    int pos = atomicAdd(&d_cur[dst], 1);
    d_csr[dst*CAP + pos] = src;
}

// ---------------- proj layer1: 128n x 64m tile, 256 thr, 8n x 4m per thread, f32x2 ----------------
__global__ void k_proj1(const float* __restrict__ Wl, const float* __restrict__ bl,
                        const float* __restrict__ Wr, const float* __restrict__ br){
    const int K = F1;
    int m0g = blockIdx.x*64;
    bool isR = (m0g >= D1);
    const float* W    = isR ? Wr : Wl;
    const float* bias = isR ? br : bl;
    int m0 = isR ? (m0g - D1) : m0g;
    float* C = isR ? d_xr1 : d_xl1;
    int n0 = blockIdx.y*128;

    __shared__ float As[16][132];
    __shared__ unsigned long long Wp[16][32];
    int tid = threadIdx.x;
    int tx = tid & 15, ty = tid >> 4;

    unsigned long long acc[8][2];
    #pragma unroll
    for (int i=0;i<8;i++){ acc[i][0]=0ull; acc[i][1]=0ull; }

    for (int k0=0; k0<K; k0+=16){
        #pragma unroll
        for (int q=0;q<2;q++){
            int lin = tid + q*256;
            int k = lin >> 5, n4 = (lin & 31)*4;
            float4 v;
            if (k0+k < K) v = *reinterpret_cast<const float4*>(&d_xnT[(k0+k)*NTOT + n0+n4]);
            else          v = make_float4(0.f,0.f,0.f,0.f);
            *reinterpret_cast<float4*>(&As[k][n4]) = v;
        }
        #pragma unroll
        for (int q=0;q<2;q++){
            int lin = tid + q*256;
            int mp = lin & 31, k = lin >> 5;
            float wa = 0.f, wb = 0.f;
            if (k0+k < K){
                wa = W[(m0+2*mp  )*K + k0+k];
                wb = W[(m0+2*mp+1)*K + k0+k];
            }
            Wp[k][mp] = pack2(wa, wb);
        }
        __syncthreads();
        #pragma unroll
        for (int kk=0;kk<16;kk++){
            float4 a0 = *reinterpret_cast<const float4*>(&As[kk][ty*8]);
            float4 a1 = *reinterpret_cast<const float4*>(&As[kk][ty*8+4]);
            ulonglong2 w = *reinterpret_cast<const ulonglong2*>(&Wp[kk][tx*2]);
            unsigned long long ap[8];
            ap[0]=pack2(a0.x,a0.x); ap[1]=pack2(a0.y,a0.y);
            ap[2]=pack2(a0.z,a0.z); ap[3]=pack2(a0.w,a0.w);
            ap[4]=pack2(a1.x,a1.x); ap[5]=pack2(a1.y,a1.y);
            ap[6]=pack2(a1.z,a1.z); ap[7]=pack2(a1.w,a1.w);
            #pragma unroll
            for (int i=0;i<8;i++){
                acc[i][0] = fma2(ap[i], w.x, acc[i][0]);
                acc[i][1] = fma2(ap[i], w.y, acc[i][1]);
            }
        }
        __syncthreads();
    }
    int m = m0 + tx*4;
    float4 bv = *reinterpret_cast<const float4*>(&bias[m]);
    #pragma unroll
    for (int i=0;i<8;i++){
        int n = n0 + ty*8 + i;
        float v0,v1,v2,v3;
        unpack2(acc[i][0], v0, v1);
        unpack2(acc[i][1], v2, v3);
        float4 r4 = make_float4(v0+bv.x, v1+bv.y, v2+bv.z, v3+bv.w);
        *reinterpret_cast<float4*>(&C[n*D1 + m]) = r4;
    }
}

// ---------------- proj layer2: 64x64 tile, 256 thr, 4n x 4m per thread, f32x2 ----------------
__global__ void k_proj2(const float* __restrict__ Wl, const float* __restrict__ bl,
                        const float* __restrict__ Wr, const float* __restrict__ br){
    const int K = D1;
    bool isR = (blockIdx.x != 0);
    const float* W    = isR ? Wr : Wl;
    const float* bias = isR ? br : bl;
    float* C = isR ? d_xr2 : d_xl2;
    int n0 = blockIdx.y*64;

    __shared__ float As[32][64];
    __shared__ unsigned long long Wp[32][32];
    int tid = threadIdx.x;
    int tx = tid & 15, ty = tid >> 4;

    unsigned long long acc[4][2];
    #pragma unroll
    for (int i=0;i<4;i++){ acc[i][0]=0ull; acc[i][1]=0ull; }

    for (int k0=0; k0<K; k0+=32){
        #pragma unroll
        for (int q=0;q<2;q++){
            int lin = tid + q*256;
            int n = lin & 63, kq = (lin >> 6)*4;
            float4 v = *reinterpret_cast<const float4*>(&d_h1[(n0+n)*D1 + k0+kq]);
            As[kq+0][n] = v.x;
            As[kq+1][n] = v.y;
            As[kq+2][n] = v.z;
            As[kq+3][n] = v.w;
        }
        #pragma unroll
        for (int q=0;q<4;q++){
            int lin = tid + q*256;
            int mp = lin >> 5, k = lin & 31;
            Wp[k][mp] = pack2(W[(2*mp  )*K + k0+k], W[(2*mp+1)*K + k0+k]);
        }
        __syncthreads();
        #pragma unroll
        for (int kk=0;kk<32;kk++){
            float4 a0 = *reinterpret_cast<const float4*>(&As[kk][ty*4]);
            ulonglong2 w01 = *reinterpret_cast<const ulonglong2*>(&Wp[kk][tx*2]);
            unsigned long long ap[4];
            ap[0]=pack2(a0.x,a0.x); ap[1]=pack2(a0.y,a0.y);
            ap[2]=pack2(a0.z,a0.z); ap[3]=pack2(a0.w,a0.w);
            #pragma unroll
            for (int i=0;i<4;i++){
                acc[i][0] = fma2(ap[i], w01.x, acc[i][0]);
                acc[i][1] = fma2(ap[i], w01.y, acc[i][1]);
            }
        }
        __syncthreads();
    }
    int m = tx*4;
    float4 bA = *reinterpret_cast<const float4*>(&bias[m]);
    #pragma unroll
    for (int i=0;i<4;i++){
        int n = n0 + ty*4 + i;
        float v0,v1,v2,v3;
        unpack2(acc[i][0], v0, v1);
        unpack2(acc[i][1], v2, v3);
        float4 r4 = make_float4(v0+bA.x, v1+bA.y, v2+bA.z, v3+bA.w);
        *reinterpret_cast<float4*>(&C[n*OUTC + m]) = r4;
    }
}

// ---------------- GAT1: lrelu folded, depth-1 software prefetch ----------------
__global__ void k_gat1(const float* __restrict__ att, const float* __restrict__ bias){
    int d = blockIdx.x;
    int h = threadIdx.x >> 5, lane = threadIdx.x & 31;
    int g = lane >> 3, l8 = lane & 7;
    int col = h*HID + l8*8;
    const float4* xr4 = reinterpret_cast<const float4*>(&d_xr1[d*D1 + col]);
    float4 xrA = xr4[0], xrB = xr4[1];
    const float4* at4 = reinterpret_cast<const float4*>(&att[col]);
    float4 atA = at4[0], atB = at4[1];
    float4 pA = make_float4(0.6f*atA.x, 0.6f*atA.y, 0.6f*atA.z, 0.6f*atA.w);
    float4 pB = make_float4(0.6f*atB.x, 0.6f*atB.y, 0.6f*atB.z, 0.6f*atB.w);
    float4 rA_ = make_float4(0.4f*atA.x, 0.4f*atA.y, 0.4f*atA.z, 0.4f*atA.w);
    float4 rB_ = make_float4(0.4f*atB.x, 0.4f*atB.y, 0.4f*atB.z, 0.4f*atB.w);

    float den = 0.f;
    float s[8] = {0,0,0,0,0,0,0,0};
    int eb = d*CAP;
    int deg = d_cur[d];
    // prefetch iter 0
    bool v0 = (g < deg);
    int src0 = d_csr[eb + (v0 ? g : 0)];
    float4 lA = *reinterpret_cast<const float4*>(&d_xl1[src0*D1 + col]);
    float4 lB = *reinterpret_cast<const float4*>(&d_xl1[src0*D1 + col + 4]);
    for (int i0 = 0; i0 < deg; i0 += 4){
        float4 cA = lA, cB = lB;
        bool cv = (i0 + g) < deg;
        if (i0 + 4 < deg){
            int i2 = i0 + 4 + g;
            bool v2 = i2 < deg;
            int s2 = d_csr[eb + (v2 ? i2 : 0)];
            lA = *reinterpret_cast<const float4*>(&d_xl1[s2*D1 + col]);
            lB = *reinterpret_cast<const float4*>(&d_xl1[s2*D1 + col + 4]);
        }
        float t, q = 0.f;
        t = cA.x + xrA.x; q = __fmaf_rn(pA.x, t, __fmaf_rn(rA_.x, fabsf(t), q));
        t = cA.y + xrA.y; q = __fmaf_rn(pA.y, t, __fmaf_rn(rA_.y, fabsf(t), q));
        t = cA.z + xrA.z; q = __fmaf_rn(pA.z, t, __fmaf_rn(rA_.z, fabsf(t), q));
        t = cA.w + xrA.w; q = __fmaf_rn(pA.w, t, __fmaf_rn(rA_.w, fabsf(t), q));
        t = cB.x + xrB.x; q = __fmaf_rn(pB.x, t, __fmaf_rn(rB_.x, fabsf(t), q));
        t = cB.y + xrB.y; q = __fmaf_rn(pB.y, t, __fmaf_rn(rB_.y, fabsf(t), q));
        t = cB.z + xrB.z; q = __fmaf_rn(pB.z, t, __fmaf_rn(rB_.z, fabsf(t), q));
        t = cB.w + xrB.w; q = __fmaf_rn(pB.w, t, __fmaf_rn(rB_.w, fabsf(t), q));
        q += __shfl_xor_sync(0xffffffffu, q, 1);
        q += __shfl_xor_sync(0xffffffffu, q, 2);
        q += __shfl_xor_sync(0xffffffffu, q, 4);
        float wv = cv ? __expf(q) : 0.f;
        den += wv;
        s[0] += wv*cA.x; s[1] += wv*cA.y; s[2] += wv*cA.z; s[3] += wv*cA.w;
        s[4] += wv*cB.x; s[5] += wv*cB.y; s[6] += wv*cB.z; s[7] += wv*cB.w;
    }
    #pragma unroll
    for (int o=8;o<=16;o<<=1){
        den += __shfl_xor_sync(0xffffffffu, den, o);
        #pragma unroll
        for (int k=0;k<8;k++) s[k] += __shfl_xor_sync(0xffffffffu, s[k], o);
    }
    if (g == 0){
        float inv = __fdividef(1.f, den);
        float o0;
        float4 rA, rB;
        o0 = s[0]*inv + bias[col+0]; rA.x = o0>0.f? o0 : (__expf(o0)-1.f);
        o0 = s[1]*inv + bias[col+1]; rA.y = o0>0.f? o0 : (__expf(o0)-1.f);
        o0 = s[2]*inv + bias[col+2]; rA.z = o0>0.f? o0 : (__expf(o0)-1.f);
        o0 = s[3]*inv + bias[col+3]; rA.w = o0>0.f? o0 : (__expf(o0)-1.f);
        o0 = s[4]*inv + bias[col+4]; rB.x = o0>0.f? o0 : (__expf(o0)-1.f);
        o0 = s[5]*inv + bias[col+5]; rB.y = o0>0.f? o0 : (__expf(o0)-1.f);
        o0 = s[6]*inv + bias[col+6]; rB.z = o0>0.f? o0 : (__expf(o0)-1.f);
        o0 = s[7]*inv + bias[col+7]; rB.w = o0>0.f? o0 : (__expf(o0)-1.f);
        float4* dst = reinterpret_cast<float4*>(&d_h1[d*D1 + col]);
        dst[0] = rA; dst[1] = rB;
    }
}

// ---------------- GAT2: warp per dst, lrelu folded, depth-1 prefetch ----------------
__global__ void k_gat2(const float* __restrict__ att, const float* __restrict__ bias,
                       float* __restrict__ out){
    int d = blockIdx.x*8 + (threadIdx.x>>5);
    int lane = threadIdx.x & 31;
    if (d >= NTOT) return;
    int g = lane >> 3, l8 = lane & 7;
    int col = l8*8;
    const float4* xr4 = reinterpret_cast<const float4*>(&d_xr2[d*OUTC + col]);
    float4 xrA = xr4[0], xrB = xr4[1];
    const float4* at4 = reinterpret_cast<const float4*>(&att[col]);
    float4 atA = at4[0], atB = at4[1];
    float4 pA = make_float4(0.6f*atA.x, 0.6f*atA.y, 0.6f*atA.z, 0.6f*atA.w);
    float4 pB = make_float4(0.6f*atB.x, 0.6f*atB.y, 0.6f*atB.z, 0.6f*atB.w);
    float4 rA_ = make_float4(0.4f*atA.x, 0.4f*atA.y, 0.4f*atA.z, 0.4f*atA.w);
    float4 rB_ = make_float4(0.4f*atB.x, 0.4f*atB.y, 0.4f*atB.z, 0.4f*atB.w);

    float den = 0.f;
    float s[8] = {0,0,0,0,0,0,0,0};
    int eb = d*CAP;
    int deg = d_cur[d];
    bool v0 = (g < deg);
    int src0 = d_csr[eb + (v0 ? g : 0)];
    float4 lA = *reinterpret_cast<const float4*>(&d_xl2[src0*OUTC + col]);
    float4 lB = *reinterpret_cast<const float4*>(&d_xl2[src0*OUTC + col + 4]);
    for (int i0 = 0; i0 < deg; i0 += 4){
        float4 cA = lA, cB = lB;
        bool cv = (i0 + g) < deg;
        if (i0 + 4 < deg){
            int i2 = i0 + 4 + g;
            bool v2 = i2 < deg;
            int s2 = d_csr[eb + (v2 ? i2 : 0)];
            lA = *reinterpret_cast<const float4*>(&d_xl2[s2*OUTC + col]);
            lB = *reinterpret_cast<const float4*>(&d_xl2[s2*OUTC + col + 4]);
        }
        float t, q = 0.f;
        t = cA.x + xrA.x; q = __fmaf_rn(pA.x, t, __fmaf_rn(rA_.x, fabsf(t), q));
        t = cA.y + xrA.y; q = __fmaf_rn(pA.y, t, __fmaf_rn(rA_.y, fabsf(t), q));
        t = cA.z + xrA.z; q = __fmaf_rn(pA.z, t, __fmaf_rn(rA_.z, fabsf(t), q));
        t = cA.w + xrA.w; q = __fmaf_rn(pA.w, t, __fmaf_rn(rA_.w, fabsf(t), q));
        t = cB.x + xrB.x; q = __fmaf_rn(pB.x, t, __fmaf_rn(rB_.x, fabsf(t), q));
        t = cB.y + xrB.y; q = __fmaf_rn(pB.y, t, __fmaf_rn(rB_.y, fabsf(t), q));
        t = cB.z + xrB.z; q = __fmaf_rn(pB.z, t, __fmaf_rn(rB_.z, fabsf(t), q));
        t = cB.w + xrB.w; q = __fmaf_rn(pB.w, t, __fmaf_rn(rB_.w, fabsf(t), q));
        q += __shfl_xor_sync(0xffffffffu, q, 1);
        q += __shfl_xor_sync(0xffffffffu, q, 2);
        q += __shfl_xor_sync(0xffffffffu, q, 4);
        float wv = cv ? __expf(q) : 0.f;
        den += wv;
        s[0] += wv*cA.x; s[1] += wv*cA.y; s[2] += wv*cA.z; s[3] += wv*cA.w;
        s[4] += wv*cB.x; s[5] += wv*cB.y; s[6] += wv*cB.z; s[7] += wv*cB.w;
    }
    #pragma unroll
    for (int o=8;o<=16;o<<=1){
        den += __shfl_xor_sync(0xffffffffu, den, o);
        #pragma unroll
        for (int k=0;k<8;k++) s[k] += __shfl_xor_sync(0xffffffffu, s[k], o);
    }
    if (g == 0){
        float inv = __fdividef(1.f, den);
        float4 rA, rB;
        rA.x = s[0]*inv + bias[col+0];
        rA.y = s[1]*inv + bias[col+1];
        rA.z = s[2]*inv + bias[col+2];
        rA.w = s[3]*inv + bias[col+3];
        rB.x = s[4]*inv + bias[col+4];
        rB.y = s[5]*inv + bias[col+5];
        rB.z = s[6]*inv + bias[col+6];
        rB.w = s[7]*inv + bias[col+7];
        float4* dst = reinterpret_cast<float4*>(&out[d*OUTC + col]);
        dst[0] = rA; dst[1] = rB;
    }
}

// ---------------- host launch ----------------
extern "C" void kernel_launch(void* const* d_in, const int* in_sizes, int n_in,
                              void* d_out, int out_size){
    const int*   eib   = (const int*)d_in[0];
    const float* ve    = (const float*)d_in[1];
    const float* ac    = (const float*)d_in[2];
    const float* man   = (const float*)d_in[3];
    const float* mask  = (const float*)d_in[4];
    const float* c1w   = (const float*)d_in[6];
    const float* c1b   = (const float*)d_in[7];
    const float* bn1g  = (const float*)d_in[8];
    const float* bn1b  = (const float*)d_in[9];
    const float* c2w   = (const float*)d_in[10];
    const float* c2b   = (const float*)d_in[11];
    const float* bn2g  = (const float*)d_in[12];
    const float* bn2b  = (const float*)d_in[13];
    const float* gwih  = (const float*)d_in[14];
    const float* gwhh  = (const float*)d_in[15];
    const float* gbih  = (const float*)d_in[16];
    const float* gbhh  = (const float*)d_in[17];
    const float* g1wl  = (const float*)d_in[18];
    const float* g1bl  = (const float*)d_in[19];
    const float* g1wr  = (const float*)d_in[20];
    const float* g1br  = (const float*)d_in[21];
    const float* g1att = (const float*)d_in[22];
    const float* g1bias= (const float*)d_in[23];
    const float* g2wl  = (const float*)d_in[24];
    const float* g2bl  = (const float*)d_in[25];
    const float* g2wr  = (const float*)d_in[26];
    const float* g2br  = (const float*)d_in[27];
    const float* g2att = (const float*)d_in[28];
    const float* g2bias= (const float*)d_in[29];
    float* out = (float*)d_out;

    // conv2 in profiled slot 4
    k_conv1<<<(BB*POS+255)/256, 256>>>(man, ac, ve, mask, c1w, c1b, bn1g, bn1b);
    k_init<<<(NTOT+255)/256, 256>>>();
    k_scatter<<<(ET+255)/256, 256>>>(eib);
    k_conv2<<<dim3(BB, (POS2+255)/256), 256>>>(c2w, c2b, bn2g, bn2b, gwih, gbih);
    k_gru<<<(NTOT+63)/64, 64>>>(mask, gwhh, gbhh);
    k_proj1<<<dim3(2*D1/64, NTOT/128), 256>>>(g1wl, g1bl, g1wr, g1br);
    k_gat1<<<NTOT, 256>>>(g1att, g1bias);
    k_proj2<<<dim3(2, NTOT/64), 256>>>(g2wl, g2bl, g2wr, g2br);
    k_gat2<<<(NTOT+7)/8, 256>>>(g2att, g2bias, out);
}